// round 1
// baseline (speedup 1.0000x reference)
#include <cuda_runtime.h>

// MMDLoss / energy-distance:
//   loss = mean_b [ mean_ij d(x_i,y_j) - 0.5*mean_ij d(x_i,x_j) - 0.5*mean_ij d(y_i,y_j) ]
// with B=128 batches, n=512 points, D=128, d = sqrt(max(d2,0)),
// d2_ij = |x_i|^2 + |y_j|^2 - 2 x_i.y_j.
//
// Strategy:
//  - kernel 0: per-row squared norms (fp32 exact)
//  - kernel 1: tiled Gram + fused sqrt + per-CTA sum.
//      cross: full 4x4 tiling of 512x512 per batch (2048 CTAs)
//      xx/yy: upper-triangle tiles only (10 per batch each -> 2560 CTAs),
//             strict upper (j>i) inside diagonal tiles; weight -1.
//  - kernel 2: deterministic double-precision reduction of 4608 partials.
// loss = (S_cross - S_xx_ut - S_yy_ut) / (128*512*512)

#define NPTS  512
#define DIMS  128
#define NB    128
#define NROWS 65536            // NB * NPTS
#define N_CROSS_CTAS 2048      // 128 batches * 16 tiles
#define N_SELF_CTAS  1280      // 128 batches * 10 upper-tri tiles
#define N_CTAS (N_CROSS_CTAS + 2 * N_SELF_CTAS)   // 4608

__device__ float g_norm_x[NROWS];
__device__ float g_norm_y[NROWS];
__device__ float g_partials[N_CTAS];

// ---------------------------------------------------------------------------
// Kernel 0: squared norms, one warp per row (128 floats = 32 float4, 1/lane)
// ---------------------------------------------------------------------------
__global__ void norms_kernel(const float* __restrict__ X,
                             const float* __restrict__ Y) {
    int gw   = (blockIdx.x * blockDim.x + threadIdx.x) >> 5;  // global warp id
    int lane = threadIdx.x & 31;
    const float* src;
    float* dst;
    int row;
    if (gw < NROWS) { src = X; dst = g_norm_x; row = gw; }
    else            { src = Y; dst = g_norm_y; row = gw - NROWS; }

    float4 v = ((const float4*)(src + (long)row * DIMS))[lane];
    float s = v.x * v.x + v.y * v.y + v.z * v.z + v.w * v.w;
#pragma unroll
    for (int o = 16; o; o >>= 1) s += __shfl_xor_sync(0xffffffffu, s, o);
    if (lane == 0) dst[row] = s;
}

// ---------------------------------------------------------------------------
// Kernel 1: 128x128 tile of a distance matrix, K=128, fused sqrt + CTA sum.
// 256 threads, 8x8 register micro-tile per thread (split halves for
// conflict-free float4 smem reads).
// ---------------------------------------------------------------------------
__global__ __launch_bounds__(256, 2)
void dist_kernel(const float* __restrict__ X, const float* __restrict__ Y) {
    __shared__ float As[32][128];   // k-major: As[k][i]
    __shared__ float Bs[32][128];   // k-major: Bs[k][j]
    __shared__ float red[8];

    int job = blockIdx.x;
    const float *Ap, *Bp, *nAp, *nBp;
    int b, tr, tc;
    bool selfm;
    if (job < N_CROSS_CTAS) {
        b = job >> 4;
        int t = job & 15;
        tr = t >> 2; tc = t & 3;
        Ap = X; Bp = Y; nAp = g_norm_x; nBp = g_norm_y;
        selfm = false;
    } else {
        int r = job - N_CROSS_CTAS;
        int isY = (r >= N_SELF_CTAS);
        if (isY) r -= N_SELF_CTAS;
        b = r / 10;
        int t = r - b * 10;
        // t -> (tr, tc) over upper triangle (incl. diagonal) of 4x4 tiles
        int trr = 0, tt = t;
        while (tt >= 4 - trr) { tt -= 4 - trr; trr++; }
        tr = trr; tc = trr + tt;
        Ap = isY ? Y : X;
        Bp = Ap;
        nAp = isY ? g_norm_y : g_norm_x;
        nBp = nAp;
        selfm = true;
    }

    const float* Abase = Ap + ((long)b * NPTS + tr * 128) * DIMS;
    const float* Bbase = Bp + ((long)b * NPTS + tc * 128) * DIMS;

    int tid = threadIdx.x;
    int tx = tid & 15, ty = tid >> 4;

    float acc[8][8];
#pragma unroll
    for (int i = 0; i < 8; i++)
#pragma unroll
        for (int j = 0; j < 8; j++) acc[i][j] = 0.f;

    int lkv = tid & 7;      // which float4 within a 32-wide k-chunk
    int li0 = tid >> 3;     // starting row (0..31), step 32

    for (int kc = 0; kc < DIMS; kc += 32) {
        __syncthreads();
#pragma unroll 4
        for (int i = li0; i < 128; i += 32) {
            float4 va = *(const float4*)(Abase + (long)i * DIMS + kc + lkv * 4);
            As[lkv * 4 + 0][i] = va.x;
            As[lkv * 4 + 1][i] = va.y;
            As[lkv * 4 + 2][i] = va.z;
            As[lkv * 4 + 3][i] = va.w;
            float4 vb = *(const float4*)(Bbase + (long)i * DIMS + kc + lkv * 4);
            Bs[lkv * 4 + 0][i] = vb.x;
            Bs[lkv * 4 + 1][i] = vb.y;
            Bs[lkv * 4 + 2][i] = vb.z;
            Bs[lkv * 4 + 3][i] = vb.w;
        }
        __syncthreads();
#pragma unroll
        for (int k = 0; k < 32; k++) {
            float4 a0 = *(const float4*)&As[k][ty * 4];
            float4 a1 = *(const float4*)&As[k][64 + ty * 4];
            float4 b0 = *(const float4*)&Bs[k][tx * 4];
            float4 b1 = *(const float4*)&Bs[k][64 + tx * 4];
            float ar[8] = {a0.x, a0.y, a0.z, a0.w, a1.x, a1.y, a1.z, a1.w};
            float br[8] = {b0.x, b0.y, b0.z, b0.w, b1.x, b1.y, b1.z, b1.w};
#pragma unroll
            for (int i = 0; i < 8; i++)
#pragma unroll
                for (int j = 0; j < 8; j++)
                    acc[i][j] = fmaf(ar[i], br[j], acc[i][j]);
        }
    }

    // Epilogue: d2 = nx + ny - 2*dot ; d = sqrt via d2*rsqrt(d2); mask; sum.
    int irow[8], jcol[8];
    float nx[8], ny[8];
#pragma unroll
    for (int i = 0; i < 8; i++) {
        int iloc = (i >> 2) * 64 + ty * 4 + (i & 3);
        irow[i] = tr * 128 + iloc;                 // row within batch [0,512)
        nx[i] = nAp[b * NPTS + irow[i]];
        int jloc = (i >> 2) * 64 + tx * 4 + (i & 3);
        jcol[i] = tc * 128 + jloc;
        ny[i] = nBp[b * NPTS + jcol[i]];
    }

    float tsum = 0.f;
#pragma unroll
    for (int i = 0; i < 8; i++)
#pragma unroll
        for (int j = 0; j < 8; j++) {
            float d2 = nx[i] + ny[j] - 2.f * acc[i][j];
            float d = (d2 > 0.f) ? d2 * rsqrtf(d2) : 0.f;
            if (selfm && jcol[j] <= irow[i]) d = 0.f;   // strict upper only
            tsum += d;
        }

#pragma unroll
    for (int o = 16; o; o >>= 1) tsum += __shfl_xor_sync(0xffffffffu, tsum, o);
    if ((tid & 31) == 0) red[tid >> 5] = tsum;
    __syncthreads();
    if (tid == 0) {
        float s = 0.f;
#pragma unroll
        for (int w = 0; w < 8; w++) s += red[w];
        g_partials[blockIdx.x] = s;
    }
}

// ---------------------------------------------------------------------------
// Kernel 2: deterministic double-precision finalize.
// ---------------------------------------------------------------------------
__global__ void finalize_kernel(float* __restrict__ out) {
    __shared__ double sd[256];
    int tid = threadIdx.x;
    double s = 0.0;
    for (int i = tid; i < N_CTAS; i += 256) {
        double v = (double)g_partials[i];
        s += (i < N_CROSS_CTAS) ? v : -v;
    }
    sd[tid] = s;
    __syncthreads();
    for (int o = 128; o; o >>= 1) {
        if (tid < o) sd[tid] += sd[tid + o];
        __syncthreads();
    }
    if (tid == 0)
        out[0] = (float)(sd[0] / ((double)NB * NPTS * NPTS));  // / 33554432
}

// ---------------------------------------------------------------------------
extern "C" void kernel_launch(void* const* d_in, const int* in_sizes, int n_in,
                              void* d_out, int out_size) {
    const float* X = (const float*)d_in[0];   // input  (65536,128) fp32
    const float* Y = (const float*)d_in[1];   // target (65536,128) fp32

    // 2*65536 rows, one warp per row, 8 warps per block
    norms_kernel<<<(2 * NROWS) / 8, 256>>>(X, Y);
    dist_kernel<<<N_CTAS, 256>>>(X, Y);
    finalize_kernel<<<1, 256>>>((float*)d_out);
}

// round 2
// speedup vs baseline: 4.1983x; 4.1983x over previous
#include <cuda_runtime.h>
#include <cuda_bf16.h>

// Energy-distance loss, tensor-core version.
//   loss = mean_b [ mean||x-y|| - 0.5 mean||x-x'|| - 0.5 mean||y-y'|| ]
// Gram matrices via bf16 mma.sync (fp32 accum), norms fp32-exact,
// diagonal excluded analytically (strict upper triangle, weight -1).

#define NPTS  512
#define DIMS  128
#define NB    128
#define NROWS 65536
#define N_CROSS_CTAS 2048      // 128 batches * 16 tiles
#define N_SELF_CTAS  1280      // 128 batches * 10 upper-tri tiles
#define N_CTAS (N_CROSS_CTAS + 2 * N_SELF_CTAS)   // 4608

__device__ __nv_bfloat16 g_bx[NROWS * DIMS];   // 16 MB
__device__ __nv_bfloat16 g_by[NROWS * DIMS];   // 16 MB
__device__ float g_norm_x[NROWS];
__device__ float g_norm_y[NROWS];
__device__ float g_partials[N_CTAS];

// ---------------------------------------------------------------------------
// Kernel 0: fp32 -> bf16 convert + exact fp32 squared norms.
// 8 warps/block, 4 rows per warp (MLP=4 to beat the R1 latency bind).
// ---------------------------------------------------------------------------
__global__ void prep_kernel(const float* __restrict__ X,
                            const float* __restrict__ Y) {
    int warp = (blockIdx.x * blockDim.x + threadIdx.x) >> 5;
    int lane = threadIdx.x & 31;
    int row4 = warp * 4;
    const float* src; __nv_bfloat16* dst; float* ndst; int r0;
    if (row4 < NROWS) { src = X; dst = g_bx; ndst = g_norm_x; r0 = row4; }
    else              { src = Y; dst = g_by; ndst = g_norm_y; r0 = row4 - NROWS; }

    float4 v[4];
    float s[4];
#pragma unroll
    for (int k = 0; k < 4; k++) {
        v[k] = ((const float4*)(src + (size_t)(r0 + k) * DIMS))[lane];
        s[k] = v[k].x * v[k].x + v[k].y * v[k].y + v[k].z * v[k].z + v[k].w * v[k].w;
    }
#pragma unroll
    for (int k = 0; k < 4; k++) {
        __nv_bfloat162 lo = __floats2bfloat162_rn(v[k].x, v[k].y);
        __nv_bfloat162 hi = __floats2bfloat162_rn(v[k].z, v[k].w);
        uint2 p;
        p.x = *(unsigned*)&lo;
        p.y = *(unsigned*)&hi;
        *(uint2*)(dst + (size_t)(r0 + k) * DIMS + lane * 4) = p;
#pragma unroll
        for (int o = 16; o; o >>= 1) s[k] += __shfl_xor_sync(0xffffffffu, s[k], o);
        if (lane == 0) ndst[r0 + k] = s[k];
    }
}

// ---------------------------------------------------------------------------
// Kernel 1: one 128x128 distance tile per CTA via bf16 mma.sync, fused
// sqrt epilogue on register accumulators, per-CTA sum.
// 8 warps in 4x2; warp tile 32x64 = 2(m) x 8(n) m16n8k16 tiles.
// K=128 staged as two 64-wide smem chunks, XOR-swizzled for ldmatrix.
// ---------------------------------------------------------------------------
__global__ __launch_bounds__(256, 2)
void dist_kernel() {
    __shared__ __nv_bfloat16 As[128 * 64];   // 16 KB, swizzled
    __shared__ __nv_bfloat16 Bs[128 * 64];   // 16 KB, swizzled
    __shared__ float red[8];

    // ---- job decode ----
    int job = blockIdx.x;
    const __nv_bfloat16 *Ap, *Bp;
    const float *nAp, *nBp;
    int b, tr, tc;
    bool selfm;
    if (job < N_CROSS_CTAS) {
        b = job >> 4;
        int t = job & 15;
        tr = t >> 2; tc = t & 3;
        Ap = g_bx; Bp = g_by; nAp = g_norm_x; nBp = g_norm_y;
        selfm = false;
    } else {
        int r = job - N_CROSS_CTAS;
        int isY = (r >= N_SELF_CTAS);
        if (isY) r -= N_SELF_CTAS;
        b = r / 10;
        int t = r - b * 10;
        int trr = 0, tt = t;
        while (tt >= 4 - trr) { tt -= 4 - trr; trr++; }
        tr = trr; tc = trr + tt;
        Ap = isY ? g_by : g_bx;
        Bp = Ap;
        nAp = isY ? g_norm_y : g_norm_x;
        nBp = nAp;
        selfm = true;
    }

    const __nv_bfloat16* Abase = Ap + ((size_t)b * NPTS + tr * 128) * DIMS;
    const __nv_bfloat16* Bbase = Bp + ((size_t)b * NPTS + tc * 128) * DIMS;

    int tid  = threadIdx.x;
    int lane = tid & 31;
    int warp = tid >> 5;
    int wm   = warp >> 1;      // 0..3 -> 32-row band
    int wn   = warp & 1;       // 0..1 -> 64-col band

    float acc[2][8][4];
#pragma unroll
    for (int mt = 0; mt < 2; mt++)
#pragma unroll
        for (int nt = 0; nt < 8; nt++)
#pragma unroll
            for (int c = 0; c < 4; c++) acc[mt][nt][c] = 0.f;

    unsigned sA = (unsigned)__cvta_generic_to_shared(As);
    unsigned sB = (unsigned)__cvta_generic_to_shared(Bs);

    // ldmatrix lane-address components
    int a_r = (lane & 7) + ((lane >> 3) & 1) * 8;  // + wm*32 + mt*16
    int a_u = lane >> 4;                           // + kk*2
    int b_r = (lane & 7) + ((lane >> 4) << 3);     // + wn*64 + p*16
    int b_u = (lane >> 3) & 1;                     // + kk*2

    for (int kc = 0; kc < DIMS; kc += 64) {
        __syncthreads();
        // stage 128 rows x 64 cols of A and B, 16B units, XOR swizzle
#pragma unroll
        for (int q = 0; q < 4; q++) {
            int uid = tid + q * 256;       // 0..1023
            int r = uid >> 3, u = uid & 7;
            int soff = r * 64 + ((u ^ (r & 7)) << 3);
            *(uint4*)(As + soff) = *(const uint4*)(Abase + (size_t)r * DIMS + kc + u * 8);
            *(uint4*)(Bs + soff) = *(const uint4*)(Bbase + (size_t)r * DIMS + kc + u * 8);
        }
        __syncthreads();

#pragma unroll
        for (int kk = 0; kk < 4; kk++) {           // four k16 chunks
            unsigned af[2][4];
#pragma unroll
            for (int mt = 0; mt < 2; mt++) {
                int r = wm * 32 + mt * 16 + a_r;
                int u = kk * 2 + a_u;
                unsigned addr = sA + (unsigned)(r * 64 + ((u ^ (r & 7)) << 3)) * 2u;
                asm volatile(
                    "ldmatrix.sync.aligned.m8n8.x4.shared.b16 {%0,%1,%2,%3}, [%4];"
                    : "=r"(af[mt][0]), "=r"(af[mt][1]), "=r"(af[mt][2]), "=r"(af[mt][3])
                    : "r"(addr));
            }
#pragma unroll
            for (int p = 0; p < 4; p++) {          // n-tile pairs {2p, 2p+1}
                int r = wn * 64 + p * 16 + b_r;
                int u = kk * 2 + b_u;
                unsigned addr = sB + (unsigned)(r * 64 + ((u ^ (r & 7)) << 3)) * 2u;
                unsigned bf[4];
                asm volatile(
                    "ldmatrix.sync.aligned.m8n8.x4.shared.b16 {%0,%1,%2,%3}, [%4];"
                    : "=r"(bf[0]), "=r"(bf[1]), "=r"(bf[2]), "=r"(bf[3])
                    : "r"(addr));
#pragma unroll
                for (int mt = 0; mt < 2; mt++) {
                    asm volatile(
                        "mma.sync.aligned.m16n8k16.row.col.f32.bf16.bf16.f32 "
                        "{%0,%1,%2,%3}, {%4,%5,%6,%7}, {%8,%9}, {%0,%1,%2,%3};"
                        : "+f"(acc[mt][2*p][0]), "+f"(acc[mt][2*p][1]),
                          "+f"(acc[mt][2*p][2]), "+f"(acc[mt][2*p][3])
                        : "r"(af[mt][0]), "r"(af[mt][1]), "r"(af[mt][2]), "r"(af[mt][3]),
                          "r"(bf[0]), "r"(bf[1]));
                    asm volatile(
                        "mma.sync.aligned.m16n8k16.row.col.f32.bf16.bf16.f32 "
                        "{%0,%1,%2,%3}, {%4,%5,%6,%7}, {%8,%9}, {%0,%1,%2,%3};"
                        : "+f"(acc[mt][2*p+1][0]), "+f"(acc[mt][2*p+1][1]),
                          "+f"(acc[mt][2*p+1][2]), "+f"(acc[mt][2*p+1][3])
                        : "r"(af[mt][0]), "r"(af[mt][1]), "r"(af[mt][2]), "r"(af[mt][3]),
                          "r"(bf[2]), "r"(bf[3]));
                }
            }
        }
    }

    // ---- epilogue: d = sqrt(nx + ny - 2*dot), strict-upper mask for self ----
    int g  = lane >> 2;
    int ct = lane & 3;

    int   irow[2][2];
    float nx[2][2];
#pragma unroll
    for (int mt = 0; mt < 2; mt++) {
        irow[mt][0] = tr * 128 + wm * 32 + mt * 16 + g;
        irow[mt][1] = irow[mt][0] + 8;
        nx[mt][0] = nAp[b * NPTS + irow[mt][0]];
        nx[mt][1] = nAp[b * NPTS + irow[mt][1]];
    }
    int   jcol[8][2];
    float ny[8][2];
#pragma unroll
    for (int nt = 0; nt < 8; nt++) {
        jcol[nt][0] = tc * 128 + wn * 64 + nt * 8 + 2 * ct;
        jcol[nt][1] = jcol[nt][0] + 1;
        ny[nt][0] = nBp[b * NPTS + jcol[nt][0]];
        ny[nt][1] = nBp[b * NPTS + jcol[nt][1]];
    }

    float tsum = 0.f;
#pragma unroll
    for (int mt = 0; mt < 2; mt++)
#pragma unroll
        for (int nt = 0; nt < 8; nt++)
#pragma unroll
            for (int c = 0; c < 4; c++) {
                int ri = c >> 1;       // 0: row g, 1: row g+8
                int cj = c & 1;        // 0: col 2ct, 1: col 2ct+1
                float d2 = nx[mt][ri] + ny[nt][cj] - 2.f * acc[mt][nt][c];
                float d = (d2 > 0.f) ? d2 * rsqrtf(d2) : 0.f;
                if (selfm && jcol[nt][cj] <= irow[mt][ri]) d = 0.f;
                tsum += d;
            }

#pragma unroll
    for (int o = 16; o; o >>= 1) tsum += __shfl_xor_sync(0xffffffffu, tsum, o);
    if (lane == 0) red[warp] = tsum;
    __syncthreads();
    if (tid == 0) {
        float s = 0.f;
#pragma unroll
        for (int w = 0; w < 8; w++) s += red[w];
        g_partials[blockIdx.x] = s;
    }
}

// ---------------------------------------------------------------------------
// Kernel 2: deterministic double-precision finalize.
// ---------------------------------------------------------------------------
__global__ void finalize_kernel(float* __restrict__ out) {
    __shared__ double sd[256];
    int tid = threadIdx.x;
    double s = 0.0;
    for (int i = tid; i < N_CTAS; i += 256) {
        double v = (double)g_partials[i];
        s += (i < N_CROSS_CTAS) ? v : -v;
    }
    sd[tid] = s;
    __syncthreads();
    for (int o = 128; o; o >>= 1) {
        if (tid < o) sd[tid] += sd[tid + o];
        __syncthreads();
    }
    if (tid == 0)
        out[0] = (float)(sd[0] / ((double)NB * NPTS * NPTS));
}

// ---------------------------------------------------------------------------
extern "C" void kernel_launch(void* const* d_in, const int* in_sizes, int n_in,
                              void* d_out, int out_size) {
    const float* X = (const float*)d_in[0];
    const float* Y = (const float*)d_in[1];

    prep_kernel<<<4096, 256>>>(X, Y);     // 2*65536 rows, 4 rows/warp
    dist_kernel<<<N_CTAS, 256>>>();
    finalize_kernel<<<1, 256>>>((float*)d_out);
}

// round 4
// speedup vs baseline: 4.9914x; 1.1889x over previous
#include <cuda_runtime.h>
#include <cuda_bf16.h>
#include <cstdint>

// Energy-distance loss, optimized legacy-HMMA version (tcgen05 unreachable:
// harness emits compute_103 PTX which rejects sm_103a-only instructions).
//   loss = mean_b[ mean||x-y|| - 0.5 mean||x-x'|| - 0.5 mean||y-y'|| ]
// Grams via bf16 mma.sync.m16n8k16 (fp32 accum), norms fp32-exact,
// diagonal excluded analytically (strict upper triangle, weight -1).
//
// R4 changes vs R2: single-shot K=128 smem staging via cp.async, one sync
// pair per tile, A-tile reuse across consecutive jobs (chunked schedule),
// diagonal-only masking in the epilogue.

#define NPTS  512
#define DIMS  128
#define NB    128
#define NROWS 65536
#define N_CROSS_CTAS 2048
#define N_SELF_CTAS  1280
#define N_JOBS (N_CROSS_CTAS + 2 * N_SELF_CTAS)   // 4608
#define JOBS_PER_CTA 16
#define N_CTAS ((N_JOBS + JOBS_PER_CTA - 1) / JOBS_PER_CTA)   // 288

__device__ __nv_bfloat16 g_bx[NROWS * DIMS];
__device__ __nv_bfloat16 g_by[NROWS * DIMS];
__device__ float g_norm_x[NROWS];
__device__ float g_norm_y[NROWS];
__device__ float g_partials[N_JOBS];

// smem layout (bytes, from 1024-aligned base)
#define OFF_A    0        // 32 KB: two 16KB halves (k 0..63, 64..127)
#define OFF_B    32768    // 32 KB
#define OFF_NX   65536    // 512 B
#define OFF_NY   66048    // 512 B
#define OFF_RED  66560    // 32 B
#define SMEM_REQ (1024 + 66592)

__device__ __forceinline__ uint32_t smem_u32(const void* p) {
    uint32_t a;
    asm("{ .reg .u64 t; cvta.to.shared.u64 t, %1; cvt.u32.u64 %0, t; }"
        : "=r"(a) : "l"(p));
    return a;
}

// ---------------------------------------------------------------------------
// Kernel 0: fp32 -> bf16 convert + exact fp32 squared norms.
// ---------------------------------------------------------------------------
__global__ void prep_kernel(const float* __restrict__ X,
                            const float* __restrict__ Y) {
    int warp = (blockIdx.x * blockDim.x + threadIdx.x) >> 5;
    int lane = threadIdx.x & 31;
    int row4 = warp * 4;
    const float* src; __nv_bfloat16* dst; float* ndst; int r0;
    if (row4 < NROWS) { src = X; dst = g_bx; ndst = g_norm_x; r0 = row4; }
    else              { src = Y; dst = g_by; ndst = g_norm_y; r0 = row4 - NROWS; }

    float4 v[4];
    float s[4];
#pragma unroll
    for (int k = 0; k < 4; k++) {
        v[k] = ((const float4*)(src + (size_t)(r0 + k) * DIMS))[lane];
        s[k] = v[k].x * v[k].x + v[k].y * v[k].y + v[k].z * v[k].z + v[k].w * v[k].w;
    }
#pragma unroll
    for (int k = 0; k < 4; k++) {
        __nv_bfloat162 lo = __floats2bfloat162_rn(v[k].x, v[k].y);
        __nv_bfloat162 hi = __floats2bfloat162_rn(v[k].z, v[k].w);
        uint2 p;
        p.x = *(unsigned*)&lo;
        p.y = *(unsigned*)&hi;
        *(uint2*)(dst + (size_t)(r0 + k) * DIMS + lane * 4) = p;
#pragma unroll
        for (int o = 16; o; o >>= 1) s[k] += __shfl_xor_sync(0xffffffffu, s[k], o);
        if (lane == 0) ndst[r0 + k] = s[k];
    }
}

// ---------------------------------------------------------------------------
// Kernel 1: 128x128 distance tiles via bf16 mma.sync; chunked persistent
// schedule with A-tile reuse; cp.async single-shot staging of K=128.
// 8 warps in 4(m) x 2(n); warp tile 32x64 = 2 x 8 m16n8k16.
// ---------------------------------------------------------------------------
__global__ __launch_bounds__(256, 2)
void dist_kernel() {
    extern __shared__ char dyn_smem[];
    char* sm = (char*)((((uintptr_t)dyn_smem) + 1023) & ~(uintptr_t)1023);
    uint32_t sbase = smem_u32(sm);

    int tid  = threadIdx.x;
    int lane = tid & 31;
    int warp = tid >> 5;
    int wm   = warp >> 1;      // 0..3: 32-row band
    int wn   = warp & 1;       // 0..1: 64-col band

    // ldmatrix lane-address components (row within 16x16 frag, uint4-col)
    int a_r = (lane & 7) + ((lane >> 3) & 1) * 8;
    int a_u = lane >> 4;
    int b_r = (lane & 7) + ((lane >> 4) << 3);
    int b_u = (lane >> 3) & 1;

    int j0 = blockIdx.x * JOBS_PER_CTA;
    int j1 = j0 + JOBS_PER_CTA;
    if (j1 > N_JOBS) j1 = N_JOBS;

    const __nv_bfloat16* prevAbase = (const __nv_bfloat16*)0;

    for (int job = j0; job < j1; job++) {
        // ---- job decode ----
        const __nv_bfloat16 *Ap, *Bp;
        const float *nAp, *nBp;
        int b, tr, tc;
        bool selfm;
        if (job < N_CROSS_CTAS) {
            b = job >> 4;
            int t = job & 15;
            tr = t >> 2; tc = t & 3;          // runs of 4 share (b,tr)
            Ap = g_bx; Bp = g_by; nAp = g_norm_x; nBp = g_norm_y;
            selfm = false;
        } else {
            int r = job - N_CROSS_CTAS;
            int isY = (r >= N_SELF_CTAS);
            if (isY) r -= N_SELF_CTAS;
            b = r / 10;
            int t = r - b * 10;
            int trr = 0, tt = t;
            while (tt >= 4 - trr) { tt -= 4 - trr; trr++; }
            tr = trr; tc = trr + tt;          // runs share (b,tr) too
            Ap = isY ? g_by : g_bx;
            Bp = Ap;
            nAp = isY ? g_norm_y : g_norm_x;
            nBp = nAp;
            selfm = true;
        }
        bool diag = selfm && (tr == tc);
        const __nv_bfloat16* Abase = Ap + ((size_t)b * NPTS + tr * 128) * DIMS;
        const __nv_bfloat16* Bbase = Bp + ((size_t)b * NPTS + tc * 128) * DIMS;
        bool reuseA = (Abase == prevAbase);
        prevAbase = Abase;

        __syncthreads();   // prior job fully done with smem

        // ---- stage via cp.async: 2048 uint4 each for A (if new) and B ----
        // dst halves: half h = c8>>3 at OFF + h*16384; within half the R2
        // swizzled layout (row*128B + ((u ^ (r&7))<<4)).
#pragma unroll
        for (int q = 0; q < 8; q++) {
            int idx = tid + q * 256;           // 0..2047
            int r  = idx >> 4;
            int c8 = idx & 15;
            int h  = c8 >> 3;
            int u  = c8 & 7;
            int soff = h * 16384 + r * 128 + ((u ^ (r & 7)) << 4);
            const void* srcB = (const void*)(Bbase + (size_t)r * DIMS + c8 * 8);
            asm volatile("cp.async.cg.shared.global [%0], [%1], 16;"
                         :: "r"(sbase + OFF_B + soff), "l"(srcB));
            if (!reuseA) {
                const void* srcA = (const void*)(Abase + (size_t)r * DIMS + c8 * 8);
                asm volatile("cp.async.cg.shared.global [%0], [%1], 16;"
                             :: "r"(sbase + OFF_A + soff), "l"(srcA));
            }
        }
        // norms (plain STS, covered by the post-wait syncthreads)
        if (tid < 128) {
            if (!reuseA)
                *(float*)(sm + OFF_NX + tid * 4) = nAp[b * NPTS + tr * 128 + tid];
        } else {
            *(float*)(sm + OFF_NY + (tid - 128) * 4) = nBp[b * NPTS + tc * 128 + tid - 128];
        }
        asm volatile("cp.async.commit_group;");
        asm volatile("cp.async.wait_group 0;" ::: "memory");
        __syncthreads();

        // ---- mainloop: 2 halves x 4 k16 chunks ----
        float acc[2][8][4];
#pragma unroll
        for (int mt = 0; mt < 2; mt++)
#pragma unroll
            for (int nt = 0; nt < 8; nt++)
#pragma unroll
                for (int c = 0; c < 4; c++) acc[mt][nt][c] = 0.f;

#pragma unroll
        for (int h = 0; h < 2; h++) {
            uint32_t sA = sbase + OFF_A + h * 16384;
            uint32_t sB = sbase + OFF_B + h * 16384;
#pragma unroll
            for (int kk = 0; kk < 4; kk++) {
                unsigned af[2][4];
#pragma unroll
                for (int mt = 0; mt < 2; mt++) {
                    int r = wm * 32 + mt * 16 + a_r;
                    int u = kk * 2 + a_u;
                    unsigned addr = sA + (unsigned)(r * 128 + ((u ^ (r & 7)) << 4));
                    asm volatile(
                        "ldmatrix.sync.aligned.m8n8.x4.shared.b16 {%0,%1,%2,%3}, [%4];"
                        : "=r"(af[mt][0]), "=r"(af[mt][1]), "=r"(af[mt][2]), "=r"(af[mt][3])
                        : "r"(addr));
                }
#pragma unroll
                for (int p = 0; p < 4; p++) {
                    int r = wn * 64 + p * 16 + b_r;
                    int u = kk * 2 + b_u;
                    unsigned addr = sB + (unsigned)(r * 128 + ((u ^ (r & 7)) << 4));
                    unsigned bf[4];
                    asm volatile(
                        "ldmatrix.sync.aligned.m8n8.x4.shared.b16 {%0,%1,%2,%3}, [%4];"
                        : "=r"(bf[0]), "=r"(bf[1]), "=r"(bf[2]), "=r"(bf[3])
                        : "r"(addr));
#pragma unroll
                    for (int mt = 0; mt < 2; mt++) {
                        asm volatile(
                            "mma.sync.aligned.m16n8k16.row.col.f32.bf16.bf16.f32 "
                            "{%0,%1,%2,%3}, {%4,%5,%6,%7}, {%8,%9}, {%0,%1,%2,%3};"
                            : "+f"(acc[mt][2*p][0]), "+f"(acc[mt][2*p][1]),
                              "+f"(acc[mt][2*p][2]), "+f"(acc[mt][2*p][3])
                            : "r"(af[mt][0]), "r"(af[mt][1]), "r"(af[mt][2]), "r"(af[mt][3]),
                              "r"(bf[0]), "r"(bf[1]));
                        asm volatile(
                            "mma.sync.aligned.m16n8k16.row.col.f32.bf16.bf16.f32 "
                            "{%0,%1,%2,%3}, {%4,%5,%6,%7}, {%8,%9}, {%0,%1,%2,%3};"
                            : "+f"(acc[mt][2*p+1][0]), "+f"(acc[mt][2*p+1][1]),
                              "+f"(acc[mt][2*p+1][2]), "+f"(acc[mt][2*p+1][3])
                            : "r"(af[mt][0]), "r"(af[mt][1]), "r"(af[mt][2]), "r"(af[mt][3]),
                              "r"(bf[2]), "r"(bf[3]));
                    }
                }
            }
        }

        // ---- epilogue ----
        int g  = lane >> 2;
        int ct = lane & 3;

        int   irow[2][2];
        float nx[2][2];
#pragma unroll
        for (int mt = 0; mt < 2; mt++) {
            int r0 = wm * 32 + mt * 16 + g;
            irow[mt][0] = tr * 128 + r0;
            irow[mt][1] = irow[mt][0] + 8;
            nx[mt][0] = *(const float*)(sm + OFF_NX + r0 * 4);
            nx[mt][1] = *(const float*)(sm + OFF_NX + (r0 + 8) * 4);
        }
        int   jcol[8][2];
        float ny[8][2];
#pragma unroll
        for (int nt = 0; nt < 8; nt++) {
            int c0 = wn * 64 + nt * 8 + 2 * ct;
            jcol[nt][0] = tc * 128 + c0;
            jcol[nt][1] = jcol[nt][0] + 1;
            ny[nt][0] = *(const float*)(sm + OFF_NY + c0 * 4);
            ny[nt][1] = *(const float*)(sm + OFF_NY + (c0 + 1) * 4);
        }

        float tsum = 0.f;
        if (diag) {
#pragma unroll
            for (int mt = 0; mt < 2; mt++)
#pragma unroll
                for (int nt = 0; nt < 8; nt++)
#pragma unroll
                    for (int c = 0; c < 4; c++) {
                        int ri = c >> 1, cj = c & 1;
                        float d2 = nx[mt][ri] + ny[nt][cj] - 2.f * acc[mt][nt][c];
                        float dd;
                        asm("sqrt.approx.f32 %0, %1;" : "=f"(dd) : "f"(d2));
                        if (!(d2 > 0.f) || jcol[nt][cj] <= irow[mt][ri]) dd = 0.f;
                        tsum += dd;
                    }
        } else {
#pragma unroll
            for (int mt = 0; mt < 2; mt++)
#pragma unroll
                for (int nt = 0; nt < 8; nt++)
#pragma unroll
                    for (int c = 0; c < 4; c++) {
                        int ri = c >> 1, cj = c & 1;
                        float d2 = nx[mt][ri] + ny[nt][cj] - 2.f * acc[mt][nt][c];
                        float dd;
                        asm("sqrt.approx.f32 %0, %1;" : "=f"(dd) : "f"(d2));
                        if (!(d2 > 0.f)) dd = 0.f;
                        tsum += dd;
                    }
        }

#pragma unroll
        for (int o = 16; o; o >>= 1) tsum += __shfl_xor_sync(0xffffffffu, tsum, o);
        if (lane == 0) *(float*)(sm + OFF_RED + warp * 4) = tsum;
        __syncthreads();
        if (tid == 0) {
            float s = 0.f;
#pragma unroll
            for (int w = 0; w < 8; w++) s += *(float*)(sm + OFF_RED + w * 4);
            g_partials[job] = s;
        }
    }
}

// ---------------------------------------------------------------------------
// Kernel 2: deterministic double-precision finalize.
// ---------------------------------------------------------------------------
__global__ void finalize_kernel(float* __restrict__ out) {
    __shared__ double sd[256];
    int tid = threadIdx.x;
    double s = 0.0;
    for (int i = tid; i < N_JOBS; i += 256) {
        double v = (double)g_partials[i];
        s += (i < N_CROSS_CTAS) ? v : -v;
    }
    sd[tid] = s;
    __syncthreads();
    for (int o = 128; o; o >>= 1) {
        if (tid < o) sd[tid] += sd[tid + o];
        __syncthreads();
    }
    if (tid == 0)
        out[0] = (float)(sd[0] / ((double)NB * NPTS * NPTS));
}

// ---------------------------------------------------------------------------
extern "C" void kernel_launch(void* const* d_in, const int* in_sizes, int n_in,
                              void* d_out, int out_size) {
    const float* X = (const float*)d_in[0];
    const float* Y = (const float*)d_in[1];

    cudaFuncSetAttribute(dist_kernel,
                         cudaFuncAttributeMaxDynamicSharedMemorySize, SMEM_REQ);

    prep_kernel<<<4096, 256>>>(X, Y);
    dist_kernel<<<N_CTAS, 256, SMEM_REQ>>>();
    finalize_kernel<<<1, 256>>>((float*)d_out);
}